// round 4
// baseline (speedup 1.0000x reference)
#include <cuda_runtime.h>
#include <cuda_bf16.h>

// Problem constants (match reference)
#define N_MOL   8
#define MA      24
#define DESIGN  26
#define RADIAL  15
#define MS      (RADIAL * DESIGN)        // 390 samples per atom
#define MSH     (MS / 2)                 // 195: two points per thread
#define MXP     (MA * MS)                // 9360 grid points per molecule
#define RM_C    5.0f
#define PI_F    3.14159265358979323846f

// Output layout: concat(grid [N,MXP,3], dv [N,MXP,MA,3], weights [N,MXP])
#define GRID_FLOATS (N_MOL * MXP * 3)              // 224640
#define DV_OFF      GRID_FLOATS
#define DV_FLOATS   (N_MOL * MXP * MA * 3)         // 5391360
#define W_OFF       (DV_OFF + DV_FLOATS)           // 5616000

typedef unsigned long long u64;

// ---- packed f32x2 helpers (Blackwell sm_100+; ptxas never auto-fuses) ----
__device__ __forceinline__ u64 pk(float lo, float hi) {
    u64 r; asm("mov.b64 %0, {%1, %2};" : "=l"(r) : "f"(lo), "f"(hi)); return r;
}
__device__ __forceinline__ void upk(u64 v, float& lo, float& hi) {
    asm("mov.b64 {%0, %1}, %2;" : "=f"(lo), "=f"(hi) : "l"(v));
}
__device__ __forceinline__ u64 fma2(u64 a, u64 b, u64 c) {
    u64 r; asm("fma.rn.f32x2 %0, %1, %2, %3;" : "=l"(r) : "l"(a), "l"(b), "l"(c)); return r;
}
__device__ __forceinline__ u64 mul2(u64 a, u64 b) {
    u64 r; asm("mul.rn.f32x2 %0, %1, %2;" : "=l"(r) : "l"(a), "l"(b)); return r;
}
__device__ __forceinline__ u64 add2(u64 a, u64 b) {
    u64 r; asm("add.rn.f32x2 %0, %1, %2;" : "=l"(r) : "l"(a), "l"(b)); return r;
}
__device__ __forceinline__ float rsqrt_a(float x) {
    float r; asm("rsqrt.approx.f32 %0, %1;" : "=f"(r) : "f"(x)); return r;
}

// ============================================================================
// Fused kernel: Phase 1 = Becke weights (FMA-bound, packed f32x2, 2 points
// per thread), Phase 2 = cooperative coalesced dv stores through shared
// staging. Blocks on one SM are at different phases -> FMA and LSU overlap.
// Grid: (37, 8) x 128 = 296 blocks = exactly 2 per SM.
// ============================================================================
__global__ __launch_bounds__(128)
void fused_kernel(const float* __restrict__ coords,   // [N, MA, 3]
                  const float* __restrict__ sphere,   // [DESIGN, 3]
                  const float* __restrict__ sw,       // [DESIGN]
                  float* __restrict__ out)
{
    __shared__ float cs[MA][3];
    __shared__ u64   scs2[MA][3];       // duplicated-packed coords
    __shared__ u64   srdm2[MA][MA];     // duplicated-packed 1/max(dm,1e-12)
    __shared__ float sph[DESIGN][3];
    __shared__ float sws[DESIGN];
    __shared__ float r_tab[RADIAL];
    __shared__ float w_tab[RADIAL];
    __shared__ __align__(16) float4 c18[18];  // coords row as 18 float4
    __shared__ float g6[2 * 128][6];    // grid coords, cyclic-duplicated
    __shared__ int   gps[2 * 128];      // grid-point index per staged point

    const int nmol = blockIdx.y;
    const int tid  = threadIdx.x;

    if (tid < MA * 3) cs[tid / 3][tid % 3] = coords[nmol * MA * 3 + tid];
    if (tid < DESIGN * 3) sph[tid / 3][tid % 3] = sphere[tid];
    if (tid < DESIGN) sws[tid] = sw[tid];
    if (tid < 18) c18[tid] = ((const float4*)(coords + nmol * (MA * 3)))[tid];
    if (tid < RADIAL) {
        // Gauss-Chebyshev radial quadrature + Becke transform (once per block)
        float fi  = (float)(tid + 1);
        float z   = -cosf(PI_F * (2.0f * fi - 1.0f) / (2.0f * (float)RADIAL));
        float omz = 1.0f - z;
        float r   = RM_C * (1.0f + z) / omz;
        float dr  = 2.0f * RM_C / (omz * omz);
        float w   = sqrtf(1.0f - z * z) * dr * (PI_F / (float)RADIAL);
        r_tab[tid] = r;
        w_tab[tid] = r * r * 4.0f * PI_F * w;
    }
    __syncthreads();

    for (int e = tid; e < MA * MA; e += 128) {
        int i = e / MA, j = e % MA;
        float dx = cs[i][0] - cs[j][0];
        float dy = cs[i][1] - cs[j][1];
        float dz = cs[i][2] - cs[j][2];
        float d  = sqrtf(dx * dx + dy * dy + dz * dz);
        float rc = 1.0f / fmaxf(d, 1e-12f);
        srdm2[i][j] = pk(rc, rc);
    }
    if (tid < MA * 3) {
        float v = cs[tid / 3][tid % 3];
        scs2[tid / 3][tid % 3] = pk(v, v);
    }
    __syncthreads();

    const int qbase = blockIdx.x * 128;
    const int nact  = min(128, MA * MSH - qbase);   // active threads this block
    const int q     = qbase + tid;

    // ---------------- Phase 1: Becke weights ----------------
    if (tid < nact) {
        const int am = q / MSH;
        const int k0 = q % MSH;
        const int k1 = k0 + MSH;

        const float cax = cs[am][0], cay = cs[am][1], caz = cs[am][2];

        const int a0 = k0 / DESIGN, d0 = k0 % DESIGN;
        const int a1 = k1 / DESIGN, d1 = k1 % DESIGN;
        const float r0 = r_tab[a0], wt0 = sws[d0] * w_tab[a0];
        const float r1 = r_tab[a1], wt1 = sws[d1] * w_tab[a1];
        const float gx0 = cax + r0 * sph[d0][0];
        const float gy0 = cay + r0 * sph[d0][1];
        const float gz0 = caz + r0 * sph[d0][2];
        const float gx1 = cax + r1 * sph[d1][0];
        const float gy1 = cay + r1 * sph[d1][1];
        const float gz1 = caz + r1 * sph[d1][2];

        const u64 NEG1 = pk(-1.0f, -1.0f);
        const u64 ONE  = pk(1.0f, 1.0f);
        const u64 C15  = pk(1.5f, 1.5f);
        const u64 CN05 = pk(-0.5f, -0.5f);

        const u64 gx2 = pk(gx0, gx1), gy2 = pk(gy0, gy1), gz2 = pk(gz0, gz1);

        // distances to every atom, packed (rsqrt.approx + mul)
        u64 rx2[MA];
#pragma unroll
        for (int j = 0; j < MA; j++) {
            u64 dx = fma2(scs2[j][0], NEG1, gx2);
            u64 dy = fma2(scs2[j][1], NEG1, gy2);
            u64 dz = fma2(scs2[j][2], NEG1, gz2);
            u64 s  = mul2(dx, dx);
            s = fma2(dy, dy, s);
            s = fma2(dz, dz, s);
            float s0, s1; upk(s, s0, s1);
            rx2[j] = pk(s0 * rsqrt_a(s0), s1 * rsqrt_a(s1));
        }

        // Becke cell functions, each unordered pair once (mu_ji = -mu_ij).
        // 0.5 prefactors dropped: uniform 0.5^23 scale cancels in the ratio.
        u64 cell2[MA];
#pragma unroll
        for (int j = 0; j < MA; j++) cell2[j] = ONE;

#pragma unroll
        for (int i = 0; i < MA; i++) {
#pragma unroll
            for (int j = i + 1; j < MA; j++) {
                u64 dif = fma2(rx2[j], NEG1, rx2[i]);
                u64 mu  = mul2(dif, srdm2[i][j]);
                u64 m2 = mul2(mu, mu);
                mu = mul2(mu, fma2(m2, CN05, C15));
                m2 = mul2(mu, mu);
                mu = mul2(mu, fma2(m2, CN05, C15));
                cell2[i] = mul2(cell2[i], fma2(mu, NEG1, ONE));
                cell2[j] = mul2(cell2[j], add2(mu, ONE));
            }
        }

        u64 ssum = cell2[0];
#pragma unroll
        for (int j = 1; j < MA; j++) ssum = add2(ssum, cell2[j]);

        u64 cam2 = cell2[0];
#pragma unroll
        for (int j = 1; j < MA; j++) if (j == am) cam2 = cell2[j];

        float s0, s1, c0, c1;
        upk(ssum, s0, s1);
        upk(cam2, c0, c1);
        const float v0 = __fdividef(c0, s0);
        const float v1 = __fdividef(c1, s1);

        const int gp0 = nmol * MXP + am * MS + k0;
        const int gp1 = gp0 + MSH;
        out[3 * gp0 + 0] = gx0;
        out[3 * gp0 + 1] = gy0;
        out[3 * gp0 + 2] = gz0;
        out[3 * gp1 + 0] = gx1;
        out[3 * gp1 + 1] = gy1;
        out[3 * gp1 + 2] = gz1;
        out[W_OFF + gp0] = v0 * wt0;
        out[W_OFF + gp1] = v1 * wt1;

        // stage for dv phase: cyclic-duplicated grid coords + row index
        g6[tid][0] = gx0; g6[tid][1] = gy0; g6[tid][2] = gz0;
        g6[tid][3] = gx0; g6[tid][4] = gy0; g6[tid][5] = gz0;
        g6[nact + tid][0] = gx1; g6[nact + tid][1] = gy1; g6[nact + tid][2] = gz1;
        g6[nact + tid][3] = gx1; g6[nact + tid][4] = gy1; g6[nact + tid][5] = gz1;
        gps[tid]        = gp0;
        gps[nact + tid] = gp1;
    }
    __syncthreads();

    // ---------------- Phase 2: coalesced dv stores ----------------
    // Each dv row = 18 float4 (72 floats). Element e=4r+i has component
    // (r+i)%3 of g (4 == 1 mod 3), so pattern = cyclic reads from g6.
    const int total4 = nact * 36;            // 2*nact points * 18 float4
    float4* dvbase = (float4*)(out + DV_OFF);

    for (int idx = tid; idx < total4; idx += 128) {
        const int lp = idx / 18;
        const int r  = idx - lp * 18;
        const int rm = r % 3;

        const float pa = g6[lp][rm];
        const float pb = g6[lp][rm + 1];
        const float pc = g6[lp][rm + 2];
        const float4 c4 = c18[r];

        float4 o;
        o.x = pa - c4.x;
        o.y = pb - c4.y;
        o.z = pc - c4.z;
        o.w = pa - c4.w;

        dvbase[gps[lp] * 18 + r] = o;
    }
}

extern "C" void kernel_launch(void* const* d_in, const int* in_sizes, int n_in,
                              void* d_out, int out_size)
{
    // d_in[0]: labels (int32, unused -- padding is full for every molecule)
    const float* coords = (const float*)d_in[1];
    const float* sphere = (const float*)d_in[2];
    const float* sw     = (const float*)d_in[3];
    float* out = (float*)d_out;

    dim3 gb((MA * MSH + 127) / 128, N_MOL);   // 37 x 8 = 296 blocks, 2/SM
    fused_kernel<<<gb, 128>>>(coords, sphere, sw, out);
}

// round 5
// speedup vs baseline: 1.3361x; 1.3361x over previous
#include <cuda_runtime.h>
#include <cuda_bf16.h>

// Problem constants (match reference)
#define N_MOL   8
#define MA      24
#define DESIGN  26
#define RADIAL  15
#define MS      (RADIAL * DESIGN)        // 390 samples per atom
#define MSH     (MS / 2)                 // 195
#define MXP     (MA * MS)                // 9360 grid points per molecule
#define RM_C    5.0f
#define PI_F    3.14159265358979323846f

// Output layout: concat(grid [N,MXP,3], dv [N,MXP,MA,3], weights [N,MXP])
#define GRID_FLOATS (N_MOL * MXP * 3)              // 224640
#define DV_OFF      GRID_FLOATS
#define DV_FLOATS   (N_MOL * MXP * MA * 3)         // 5391360
#define W_OFF       (DV_OFF + DV_FLOATS)           // 5616000

#define NROWS       (N_MOL * MXP)                  // 74880 grid points total
#define BECKE_BLOCKS 296                           // 37 per molecule x 8
#define DV_BLOCKS    288
#define ROWS_PER_DVB (NROWS / DV_BLOCKS)           // 260 exactly

typedef unsigned long long u64;

// ---- packed f32x2 helpers (Blackwell sm_100+) ----
__device__ __forceinline__ u64 pk(float lo, float hi) {
    u64 r; asm("mov.b64 %0, {%1, %2};" : "=l"(r) : "f"(lo), "f"(hi)); return r;
}
__device__ __forceinline__ void upk(u64 v, float& lo, float& hi) {
    asm("mov.b64 {%0, %1}, %2;" : "=f"(lo), "=f"(hi) : "l"(v));
}
__device__ __forceinline__ u64 fma2(u64 a, u64 b, u64 c) {
    u64 r; asm("fma.rn.f32x2 %0, %1, %2, %3;" : "=l"(r) : "l"(a), "l"(b), "l"(c)); return r;
}
__device__ __forceinline__ u64 mul2(u64 a, u64 b) {
    u64 r; asm("mul.rn.f32x2 %0, %1, %2;" : "=l"(r) : "l"(a), "l"(b)); return r;
}
__device__ __forceinline__ u64 add2(u64 a, u64 b) {
    u64 r; asm("add.rn.f32x2 %0, %1, %2;" : "=l"(r) : "l"(a), "l"(b)); return r;
}
__device__ __forceinline__ float rsqrt_a(float x) {
    float r; asm("rsqrt.approx.f32 %0, %1;" : "=f"(r) : "f"(x)); return r;
}

// ============================================================================
// Block-role-specialized kernel.
//   blocks [0, 296)        : Becke weights (FMA-latency heavy)
//   blocks [296, 296+288)  : grid + dv streaming stores (LSU heavy)
// The two roles are data-independent (grid coords are recomputed from inputs
// in the dv role), so they overlap on every SM: 4 blocks/SM = ~2 of each.
// ============================================================================
__global__ __launch_bounds__(128, 4)
void grid_kernel(const float* __restrict__ coords,   // [N, MA, 3]
                 const float* __restrict__ sphere,   // [DESIGN, 3]
                 const float* __restrict__ sw,       // [DESIGN]
                 float* __restrict__ out)
{
    __shared__ float sph[DESIGN][3];
    __shared__ float r_tab[RADIAL];
    __shared__ float w_tab[RADIAL];
    // becke-only
    __shared__ float cs[MA][3];
    __shared__ u64   scs2[MA][3];
    __shared__ u64   srdm2[MA][MA];
    __shared__ float sws[DESIGN];
    // dv-only
    __shared__ float g6[ROWS_PER_DVB][6];   // grid coords, cyclic-duplicated
    __shared__ short ns[ROWS_PER_DVB];      // molecule index per staged row

    const int tid = threadIdx.x;

    // common tables
    if (tid < DESIGN * 3) sph[tid / 3][tid % 3] = sphere[tid];
    if (tid < RADIAL) {
        float fi  = (float)(tid + 1);
        float z   = -cosf(PI_F * (2.0f * fi - 1.0f) / (2.0f * (float)RADIAL));
        float omz = 1.0f - z;
        float r   = RM_C * (1.0f + z) / omz;
        float dr  = 2.0f * RM_C / (omz * omz);
        float w   = sqrtf(1.0f - z * z) * dr * (PI_F / (float)RADIAL);
        r_tab[tid] = r;
        w_tab[tid] = r * r * 4.0f * PI_F * w;
    }

    if (blockIdx.x < BECKE_BLOCKS) {
        // ================= Becke weights role =================
        const int b    = blockIdx.x;
        const int nmol = b / 37;
        const int blk  = b % 37;

        if (tid < MA * 3) cs[tid / 3][tid % 3] = coords[nmol * MA * 3 + tid];
        if (tid < DESIGN) sws[tid] = sw[tid];
        __syncthreads();

        for (int e = tid; e < MA * MA; e += 128) {
            int i = e / MA, j = e % MA;
            float dx = cs[i][0] - cs[j][0];
            float dy = cs[i][1] - cs[j][1];
            float dz = cs[i][2] - cs[j][2];
            float d  = sqrtf(dx * dx + dy * dy + dz * dz);
            float rc = 1.0f / fmaxf(d, 1e-12f);
            srdm2[i][j] = pk(rc, rc);
        }
        if (tid < MA * 3) {
            float v = cs[tid / 3][tid % 3];
            scs2[tid / 3][tid % 3] = pk(v, v);
        }
        __syncthreads();

        const int qbase = blk * 128;
        const int q     = qbase + tid;
        if (q >= MA * MSH) return;

        const int am = q / MSH;
        const int k0 = q % MSH;
        const int k1 = k0 + MSH;

        const float cax = cs[am][0], cay = cs[am][1], caz = cs[am][2];

        const int a0 = k0 / DESIGN, d0 = k0 % DESIGN;
        const int a1 = k1 / DESIGN, d1 = k1 % DESIGN;
        const float r0 = r_tab[a0], wt0 = sws[d0] * w_tab[a0];
        const float r1 = r_tab[a1], wt1 = sws[d1] * w_tab[a1];
        const float gx0 = cax + r0 * sph[d0][0];
        const float gy0 = cay + r0 * sph[d0][1];
        const float gz0 = caz + r0 * sph[d0][2];
        const float gx1 = cax + r1 * sph[d1][0];
        const float gy1 = cay + r1 * sph[d1][1];
        const float gz1 = caz + r1 * sph[d1][2];

        const u64 NEG1 = pk(-1.0f, -1.0f);
        const u64 ONE  = pk(1.0f, 1.0f);
        const u64 C15  = pk(1.5f, 1.5f);
        const u64 CN05 = pk(-0.5f, -0.5f);

        const u64 gx2 = pk(gx0, gx1), gy2 = pk(gy0, gy1), gz2 = pk(gz0, gz1);

        u64 rx2[MA];
#pragma unroll
        for (int j = 0; j < MA; j++) {
            u64 dx = fma2(scs2[j][0], NEG1, gx2);
            u64 dy = fma2(scs2[j][1], NEG1, gy2);
            u64 dz = fma2(scs2[j][2], NEG1, gz2);
            u64 s  = mul2(dx, dx);
            s = fma2(dy, dy, s);
            s = fma2(dz, dz, s);
            float s0, s1; upk(s, s0, s1);
            rx2[j] = pk(s0 * rsqrt_a(s0), s1 * rsqrt_a(s1));
        }

        u64 cell2[MA];
#pragma unroll
        for (int j = 0; j < MA; j++) cell2[j] = ONE;

#pragma unroll
        for (int i = 0; i < MA; i++) {
#pragma unroll
            for (int j = i + 1; j < MA; j++) {
                u64 dif = fma2(rx2[j], NEG1, rx2[i]);
                u64 mu  = mul2(dif, srdm2[i][j]);
                u64 m2 = mul2(mu, mu);
                mu = mul2(mu, fma2(m2, CN05, C15));
                m2 = mul2(mu, mu);
                mu = mul2(mu, fma2(m2, CN05, C15));
                cell2[i] = mul2(cell2[i], fma2(mu, NEG1, ONE));
                cell2[j] = mul2(cell2[j], add2(mu, ONE));
            }
        }

        u64 ssum = cell2[0];
#pragma unroll
        for (int j = 1; j < MA; j++) ssum = add2(ssum, cell2[j]);

        u64 cam2 = cell2[0];
#pragma unroll
        for (int j = 1; j < MA; j++) if (j == am) cam2 = cell2[j];

        float s0, s1, c0, c1;
        upk(ssum, s0, s1);
        upk(cam2, c0, c1);

        const int gp0 = nmol * MXP + am * MS + k0;
        out[W_OFF + gp0]       = __fdividef(c0, s0) * wt0;
        out[W_OFF + gp0 + MSH] = __fdividef(c1, s1) * wt1;
    } else {
        // ================= grid + dv streaming role =================
        const int dvb  = blockIdx.x - BECKE_BLOCKS;
        const int gp0  = dvb * ROWS_PER_DVB;      // first global row
        __syncthreads();                           // tables ready

        // Phase A: compute grid coords for this block's 260 rows,
        // write grid section, stage cyclic-duplicated copies in shared.
        for (int lp = tid; lp < ROWS_PER_DVB; lp += 128) {
            const int gp = gp0 + lp;
            const int n  = gp / MXP;
            const int p  = gp - n * MXP;
            const int am = p / MS;
            const int k  = p - am * MS;
            const int a  = k / DESIGN;
            const int d  = k - a * DESIGN;

            const float r = r_tab[a];
            const float* ca = coords + (n * MA + am) * 3;
            const float gx = __ldg(ca + 0) + r * sph[d][0];
            const float gy = __ldg(ca + 1) + r * sph[d][1];
            const float gz = __ldg(ca + 2) + r * sph[d][2];

            out[3 * gp + 0] = gx;
            out[3 * gp + 1] = gy;
            out[3 * gp + 2] = gz;

            g6[lp][0] = gx; g6[lp][1] = gy; g6[lp][2] = gz;
            g6[lp][3] = gx; g6[lp][4] = gy; g6[lp][5] = gz;
            ns[lp] = (short)n;
        }
        __syncthreads();

        // Phase B: dv stores. dv row = 18 float4; rows contiguous, so the
        // float4 index is linear: dst4[gp0*18 + idx]. Perfect coalescing.
        const float4* c4base = (const float4*)coords;   // 18 float4 per mol
        float4* dst4 = (float4*)(out + DV_OFF) + gp0 * 18;
        const int total4 = ROWS_PER_DVB * 18;           // 4680

        for (int idx = tid; idx < total4; idx += 128) {
            const int lp = idx / 18;
            const int r  = idx - lp * 18;
            const int rm = r % 3;

            const float pa = g6[lp][rm];
            const float pb = g6[lp][rm + 1];
            const float pc = g6[lp][rm + 2];
            const float4 c4 = __ldg(c4base + ns[lp] * 18 + r);

            float4 o;
            o.x = pa - c4.x;
            o.y = pb - c4.y;
            o.z = pc - c4.z;
            o.w = pa - c4.w;
            dst4[idx] = o;
        }
    }
}

extern "C" void kernel_launch(void* const* d_in, const int* in_sizes, int n_in,
                              void* d_out, int out_size)
{
    // d_in[0]: labels (int32, unused -- padding is full for every molecule)
    const float* coords = (const float*)d_in[1];
    const float* sphere = (const float*)d_in[2];
    const float* sw     = (const float*)d_in[3];
    float* out = (float*)d_out;

    grid_kernel<<<BECKE_BLOCKS + DV_BLOCKS, 128>>>(coords, sphere, sw, out);
}

// round 6
// speedup vs baseline: 1.3638x; 1.0207x over previous
#include <cuda_runtime.h>
#include <cuda_bf16.h>

// Problem constants (match reference)
#define N_MOL   8
#define MA      24
#define DESIGN  26
#define RADIAL  15
#define MS      (RADIAL * DESIGN)        // 390 samples per atom
#define MXP     (MA * MS)                // 9360 grid points per molecule
#define RM_C    5.0f
#define PI_F    3.14159265358979323846f

// Output layout: concat(grid [N,MXP,3], dv [N,MXP,MA,3], weights [N,MXP])
#define GRID_FLOATS (N_MOL * MXP * 3)              // 224640
#define DV_OFF      GRID_FLOATS
#define DV_FLOATS   (N_MOL * MXP * MA * 3)         // 5391360
#define W_OFF       (DV_OFF + DV_FLOATS)           // 5616000

#define NROWS        (N_MOL * MXP)                 // 74880 grid points total
#define NB_PER_MOL   74                            // ceil(9360/128)
#define BECKE_BLOCKS (N_MOL * NB_PER_MOL)          // 592
#define DV_BLOCKS    288
#define ROWS_PER_DVB (NROWS / DV_BLOCKS)           // 260 exactly

typedef unsigned long long u64;

// ---- packed f32x2 helpers (Blackwell sm_100+) ----
__device__ __forceinline__ u64 pk(float lo, float hi) {
    u64 r; asm("mov.b64 %0, {%1, %2};" : "=l"(r) : "f"(lo), "f"(hi)); return r;
}
__device__ __forceinline__ void upk(u64 v, float& lo, float& hi) {
    asm("mov.b64 {%0, %1}, %2;" : "=f"(lo), "=f"(hi) : "l"(v));
}
__device__ __forceinline__ u64 fma2(u64 a, u64 b, u64 c) {
    u64 r; asm("fma.rn.f32x2 %0, %1, %2, %3;" : "=l"(r) : "l"(a), "l"(b), "l"(c)); return r;
}
__device__ __forceinline__ u64 mul2(u64 a, u64 b) {
    u64 r; asm("mul.rn.f32x2 %0, %1, %2;" : "=l"(r) : "l"(a), "l"(b)); return r;
}
__device__ __forceinline__ u64 add2(u64 a, u64 b) {
    u64 r; asm("add.rn.f32x2 %0, %1, %2;" : "=l"(r) : "l"(a), "l"(b)); return r;
}
__device__ __forceinline__ u64 swap2(u64 v) {        // (lo,hi) -> (hi,lo); ALU movs
    float lo, hi; upk(v, lo, hi); return pk(hi, lo);
}
__device__ __forceinline__ float rsqrt_a(float x) {
    float r; asm("rsqrt.approx.f32 %0, %1;" : "=f"(r) : "f"(x)); return r;
}

// ============================================================================
// Block-role-specialized kernel, atom-packed Becke math.
//   blocks [0, 592)        : Becke weights, 1 point/thread, 2 ATOMS per f32x2
//                            lane -> rx2[12] + cell2[12] = ~48 live regs ->
//                            6 blocks/SM, 2x becke warps vs R5.
//   blocks [592, 592+288)  : grid + dv streaming stores (LSU heavy)
// 880 blocks, single wave at 6/SM.
// ============================================================================
__global__ __launch_bounds__(128, 6)
void grid_kernel(const float* __restrict__ coords,   // [N, MA, 3]
                 const float* __restrict__ sphere,   // [DESIGN, 3]
                 const float* __restrict__ sw,       // [DESIGN]
                 float* __restrict__ out)
{
    __shared__ float sph[DESIGN][3];
    __shared__ float r_tab[RADIAL];
    __shared__ float w_tab[RADIAL];
    // becke-only
    __shared__ float cs[MA][3];
    __shared__ float rdm_s[MA][MA];     // 1/max(dm,1e-12)
    __shared__ u64   sA[12][12];        // (rdm[2I][2J],   rdm[2I+1][2J+1])
    __shared__ u64   sB[12][12];        // (rdm[2I][2J+1], rdm[2I+1][2J])
    __shared__ u64   scp[12][3];        // (cs[2I][d], cs[2I+1][d])
    __shared__ float sws[DESIGN];
    // dv-only
    __shared__ float g6[ROWS_PER_DVB][6];
    __shared__ short ns[ROWS_PER_DVB];

    const int tid = threadIdx.x;

    // common tables
    if (tid < DESIGN * 3) sph[tid / 3][tid % 3] = sphere[tid];
    if (tid < RADIAL) {
        float fi  = (float)(tid + 1);
        float z   = -cosf(PI_F * (2.0f * fi - 1.0f) / (2.0f * (float)RADIAL));
        float omz = 1.0f - z;
        float r   = RM_C * (1.0f + z) / omz;
        float dr  = 2.0f * RM_C / (omz * omz);
        float w   = sqrtf(1.0f - z * z) * dr * (PI_F / (float)RADIAL);
        r_tab[tid] = r;
        w_tab[tid] = r * r * 4.0f * PI_F * w;
    }

    if (blockIdx.x < BECKE_BLOCKS) {
        // ================= Becke weights role =================
        const int nmol = blockIdx.x / NB_PER_MOL;
        const int pb   = (blockIdx.x % NB_PER_MOL) * 128;

        if (tid < MA * 3) cs[tid / 3][tid % 3] = coords[nmol * MA * 3 + tid];
        if (tid < DESIGN) sws[tid] = sw[tid];
        __syncthreads();

        for (int e = tid; e < MA * MA; e += 128) {
            int i = e / MA, j = e % MA;
            float dx = cs[i][0] - cs[j][0];
            float dy = cs[i][1] - cs[j][1];
            float dz = cs[i][2] - cs[j][2];
            float d  = sqrtf(dx * dx + dy * dy + dz * dz);
            rdm_s[i][j] = 1.0f / fmaxf(d, 1e-12f);
        }
        if (tid < 36) {
            int I = tid / 3, dd = tid % 3;
            scp[I][dd] = pk(cs[2 * I][dd], cs[2 * I + 1][dd]);
        }
        __syncthreads();
        for (int e = tid; e < 144; e += 128) {
            int I = e / 12, J = e % 12;
            sA[I][J] = pk(rdm_s[2 * I][2 * J],     rdm_s[2 * I + 1][2 * J + 1]);
            sB[I][J] = pk(rdm_s[2 * I][2 * J + 1], rdm_s[2 * I + 1][2 * J]);
        }
        __syncthreads();

        const int p = pb + tid;
        if (p >= MXP) return;

        const int am = p / MS;
        const int k  = p - am * MS;
        const int a  = k / DESIGN;
        const int d  = k - a * DESIGN;

        const float r  = r_tab[a];
        const float wt = sws[d] * w_tab[a];
        const float gx = cs[am][0] + r * sph[d][0];
        const float gy = cs[am][1] + r * sph[d][1];
        const float gz = cs[am][2] + r * sph[d][2];

        const u64 NEG1 = pk(-1.0f, -1.0f);
        const u64 ONE  = pk(1.0f, 1.0f);
        const u64 C15  = pk(1.5f, 1.5f);
        const u64 CN05 = pk(-0.5f, -0.5f);

        const u64 gxx = pk(gx, gx), gyy = pk(gy, gy), gzz = pk(gz, gz);

        // distances, atom-packed: rx2[I] = (rx[2I], rx[2I+1])
        u64 rx2[12];
#pragma unroll
        for (int I = 0; I < 12; I++) {
            u64 dx = fma2(scp[I][0], NEG1, gxx);
            u64 dy = fma2(scp[I][1], NEG1, gyy);
            u64 dz = fma2(scp[I][2], NEG1, gzz);
            u64 s  = mul2(dx, dx);
            s = fma2(dy, dy, s);
            s = fma2(dz, dz, s);
            float s0, s1; upk(s, s0, s1);
            rx2[I] = pk(s0 * rsqrt_a(s0), s1 * rsqrt_a(s1));
        }

        // cell2[I] = (cell[2I], cell[2I+1]); 0.5 prefactors dropped (cancel).
        u64 cell2[12];
#pragma unroll
        for (int I = 0; I < 12; I++) cell2[I] = ONE;

#pragma unroll
        for (int I = 0; I < 12; I++) {
            // diagonal pair (2I, 2I+1), scalar (FFMA-imm rt1 path)
            {
                float rlo, rhi; upk(rx2[I], rlo, rhi);
                float mu = (rlo - rhi) * ((const float*)&sB[I][I])[0];
                float m  = mu * mu;
                mu = mu * fmaf(m, -0.5f, 1.5f);
                m  = mu * mu;
                mu = mu * fmaf(m, -0.5f, 1.5f);
                cell2[I] = mul2(cell2[I], pk(1.0f - mu, 1.0f + mu));
            }
#pragma unroll
            for (int J = I + 1; J < 12; J++) {
                // aligned lanes: mu(2I,2J), mu(2I+1,2J+1)
                u64 muA = mul2(fma2(rx2[J], NEG1, rx2[I]), sA[I][J]);
                // cross lanes:   mu(2I,2J+1), mu(2I+1,2J)
                u64 muB = mul2(fma2(swap2(rx2[J]), NEG1, rx2[I]), sB[I][J]);

                u64 m2 = mul2(muA, muA);
                muA = mul2(muA, fma2(m2, CN05, C15));
                m2  = mul2(muA, muA);
                muA = mul2(muA, fma2(m2, CN05, C15));

                m2  = mul2(muB, muB);
                muB = mul2(muB, fma2(m2, CN05, C15));
                m2  = mul2(muB, muB);
                muB = mul2(muB, fma2(m2, CN05, C15));

                cell2[I] = mul2(cell2[I], fma2(muA, NEG1, ONE));
                cell2[I] = mul2(cell2[I], fma2(muB, NEG1, ONE));
                cell2[J] = mul2(cell2[J], add2(muA, ONE));
                cell2[J] = mul2(cell2[J], add2(swap2(muB), ONE));
            }
        }

        u64 s2 = cell2[0];
#pragma unroll
        for (int I = 1; I < 12; I++) s2 = add2(s2, cell2[I]);
        float slo, shi; upk(s2, slo, shi);
        const float ssum = slo + shi;

        const int Iam = am >> 1;
        u64 cam2 = cell2[0];
#pragma unroll
        for (int I = 1; I < 12; I++) if (I == Iam) cam2 = cell2[I];
        float clo, chi; upk(cam2, clo, chi);
        const float cam = (am & 1) ? chi : clo;

        out[W_OFF + nmol * MXP + p] = __fdividef(cam, ssum) * wt;
    } else {
        // ================= grid + dv streaming role =================
        const int dvb = blockIdx.x - BECKE_BLOCKS;
        const int gp0 = dvb * ROWS_PER_DVB;
        __syncthreads();                           // tables ready

        // Phase A: grid coords for 260 rows -> grid section + shared staging
        for (int lp = tid; lp < ROWS_PER_DVB; lp += 128) {
            const int gp = gp0 + lp;
            const int n  = gp / MXP;
            const int p  = gp - n * MXP;
            const int am = p / MS;
            const int k  = p - am * MS;
            const int a  = k / DESIGN;
            const int d  = k - a * DESIGN;

            const float r = r_tab[a];
            const float* ca = coords + (n * MA + am) * 3;
            const float gx = __ldg(ca + 0) + r * sph[d][0];
            const float gy = __ldg(ca + 1) + r * sph[d][1];
            const float gz = __ldg(ca + 2) + r * sph[d][2];

            out[3 * gp + 0] = gx;
            out[3 * gp + 1] = gy;
            out[3 * gp + 2] = gz;

            g6[lp][0] = gx; g6[lp][1] = gy; g6[lp][2] = gz;
            g6[lp][3] = gx; g6[lp][4] = gy; g6[lp][5] = gz;
            ns[lp] = (short)n;
        }
        __syncthreads();

        // Phase B: dv stores, linear float4 stream (perfect coalescing)
        const float4* c4base = (const float4*)coords;   // 18 float4 per mol
        float4* dst4 = (float4*)(out + DV_OFF) + gp0 * 18;
        const int total4 = ROWS_PER_DVB * 18;           // 4680

        for (int idx = tid; idx < total4; idx += 128) {
            const int lp = idx / 18;
            const int rr = idx - lp * 18;
            const int rm = rr % 3;

            const float pa = g6[lp][rm];
            const float pb = g6[lp][rm + 1];
            const float pc = g6[lp][rm + 2];
            const float4 c4 = __ldg(c4base + ns[lp] * 18 + rr);

            float4 o;
            o.x = pa - c4.x;
            o.y = pb - c4.y;
            o.z = pc - c4.z;
            o.w = pa - c4.w;
            dst4[idx] = o;
        }
    }
}

extern "C" void kernel_launch(void* const* d_in, const int* in_sizes, int n_in,
                              void* d_out, int out_size)
{
    // d_in[0]: labels (int32, unused -- padding is full for every molecule)
    const float* coords = (const float*)d_in[1];
    const float* sphere = (const float*)d_in[2];
    const float* sw     = (const float*)d_in[3];
    float* out = (float*)d_out;

    grid_kernel<<<BECKE_BLOCKS + DV_BLOCKS, 128>>>(coords, sphere, sw, out);
}

// round 7
// speedup vs baseline: 1.3661x; 1.0017x over previous
#include <cuda_runtime.h>
#include <cuda_bf16.h>

// Problem constants (match reference)
#define N_MOL   8
#define MA      24
#define DESIGN  26
#define RADIAL  15
#define MS      (RADIAL * DESIGN)        // 390 samples per atom
#define MXP     (MA * MS)                // 9360 grid points per molecule
#define RM_C    5.0f
#define PI_F    3.14159265358979323846f

// Output layout: concat(grid [N,MXP,3], dv [N,MXP,MA,3], weights [N,MXP])
#define GRID_FLOATS (N_MOL * MXP * 3)              // 224640
#define DV_OFF      GRID_FLOATS
#define DV_FLOATS   (N_MOL * MXP * MA * 3)         // 5391360
#define W_OFF       (DV_OFF + DV_FLOATS)           // 5616000

#define NROWS        (N_MOL * MXP)                 // 74880 grid points total
#define NB_PER_MOL   74                            // ceil(9360/128)
#define BECKE_BLOCKS (N_MOL * NB_PER_MOL)          // 592
#define DV_BLOCKS    288
#define ROWS_PER_DVB (NROWS / DV_BLOCKS)           // 260 exactly

typedef unsigned long long u64;

// ---- packed f32x2 helpers (Blackwell sm_100+) ----
__device__ __forceinline__ u64 pk(float lo, float hi) {
    u64 r; asm("mov.b64 %0, {%1, %2};" : "=l"(r) : "f"(lo), "f"(hi)); return r;
}
__device__ __forceinline__ void upk(u64 v, float& lo, float& hi) {
    asm("mov.b64 {%0, %1}, %2;" : "=f"(lo), "=f"(hi) : "l"(v));
}
__device__ __forceinline__ u64 fma2(u64 a, u64 b, u64 c) {
    u64 r; asm("fma.rn.f32x2 %0, %1, %2, %3;" : "=l"(r) : "l"(a), "l"(b), "l"(c)); return r;
}
__device__ __forceinline__ u64 mul2(u64 a, u64 b) {
    u64 r; asm("mul.rn.f32x2 %0, %1, %2;" : "=l"(r) : "l"(a), "l"(b)); return r;
}
__device__ __forceinline__ u64 add2(u64 a, u64 b) {
    u64 r; asm("add.rn.f32x2 %0, %1, %2;" : "=l"(r) : "l"(a), "l"(b)); return r;
}
__device__ __forceinline__ u64 swap2(u64 v) {        // (lo,hi) -> (hi,lo); ALU movs
    float lo, hi; upk(v, lo, hi); return pk(hi, lo);
}
__device__ __forceinline__ float rsqrt_a(float x) {
    float r; asm("rsqrt.approx.f32 %0, %1;" : "=f"(r) : "f"(x)); return r;
}

// ============================================================================
// Block-role-specialized kernel, atom-packed Becke math, 8 blocks/SM target.
//   blocks [0, 592)        : Becke weights, 1 point/thread, 2 ATOMS per f32x2
//   blocks [592, 592+288)  : grid + dv streaming stores (LSU heavy)
// 880 blocks; at 8/SM capacity (1184) everything is resident in one wave,
// so every SM runs a becke+dv mix for the whole kernel.
// ============================================================================
__global__ __launch_bounds__(128, 8)
void grid_kernel(const float* __restrict__ coords,   // [N, MA, 3]
                 const float* __restrict__ sphere,   // [DESIGN, 3]
                 const float* __restrict__ sw,       // [DESIGN]
                 float* __restrict__ out)
{
    __shared__ float sph[DESIGN][3];
    __shared__ float r_tab[RADIAL];
    __shared__ float w_tab[RADIAL];
    // becke-only
    __shared__ float cs[MA][3];
    __shared__ float rdm_s[MA][MA];        // 1/max(dm,1e-12)
    __shared__ __align__(16) ulonglong2 sAB[12][12];
    //   .x = (rdm[2I][2J],   rdm[2I+1][2J+1])   (aligned lanes)
    //   .y = (rdm[2I][2J+1], rdm[2I+1][2J])     (cross lanes)
    __shared__ u64   scp[12][3];           // (cs[2I][d], cs[2I+1][d])
    __shared__ float sws[DESIGN];
    // dv-only
    __shared__ float g6[ROWS_PER_DVB][6];
    __shared__ short ns[ROWS_PER_DVB];

    const int tid = threadIdx.x;

    // common tables
    if (tid < DESIGN * 3) sph[tid / 3][tid % 3] = sphere[tid];
    if (tid < RADIAL) {
        float fi  = (float)(tid + 1);
        float z   = -cosf(PI_F * (2.0f * fi - 1.0f) / (2.0f * (float)RADIAL));
        float omz = 1.0f - z;
        float r   = RM_C * (1.0f + z) / omz;
        float dr  = 2.0f * RM_C / (omz * omz);
        float w   = sqrtf(1.0f - z * z) * dr * (PI_F / (float)RADIAL);
        r_tab[tid] = r;
        w_tab[tid] = r * r * 4.0f * PI_F * w;
    }

    if (blockIdx.x < BECKE_BLOCKS) {
        // ================= Becke weights role =================
        const int nmol = blockIdx.x / NB_PER_MOL;
        const int pb   = (blockIdx.x % NB_PER_MOL) * 128;

        if (tid < MA * 3) cs[tid / 3][tid % 3] = coords[nmol * MA * 3 + tid];
        if (tid < DESIGN) sws[tid] = sw[tid];
        __syncthreads();

        for (int e = tid; e < MA * MA; e += 128) {
            int i = e / MA, j = e % MA;
            float dx = cs[i][0] - cs[j][0];
            float dy = cs[i][1] - cs[j][1];
            float dz = cs[i][2] - cs[j][2];
            float d  = sqrtf(dx * dx + dy * dy + dz * dz);
            rdm_s[i][j] = 1.0f / fmaxf(d, 1e-12f);
        }
        if (tid < 36) {
            int I = tid / 3, dd = tid % 3;
            scp[I][dd] = pk(cs[2 * I][dd], cs[2 * I + 1][dd]);
        }
        __syncthreads();
        for (int e = tid; e < 144; e += 128) {
            int I = e / 12, J = e % 12;
            ulonglong2 v;
            v.x = pk(rdm_s[2 * I][2 * J],     rdm_s[2 * I + 1][2 * J + 1]);
            v.y = pk(rdm_s[2 * I][2 * J + 1], rdm_s[2 * I + 1][2 * J]);
            sAB[I][J] = v;
        }
        __syncthreads();

        const int p = pb + tid;
        if (p >= MXP) return;

        const int am = p / MS;
        const int k  = p - am * MS;
        const int a  = k / DESIGN;
        const int d  = k - a * DESIGN;

        const float r  = r_tab[a];
        const float wt = sws[d] * w_tab[a];
        const float gx = cs[am][0] + r * sph[d][0];
        const float gy = cs[am][1] + r * sph[d][1];
        const float gz = cs[am][2] + r * sph[d][2];

        const u64 NEG1 = pk(-1.0f, -1.0f);
        const u64 ONE  = pk(1.0f, 1.0f);
        const u64 C15  = pk(1.5f, 1.5f);
        const u64 CN05 = pk(-0.5f, -0.5f);

        const u64 gxx = pk(gx, gx), gyy = pk(gy, gy), gzz = pk(gz, gz);

        // distances, atom-packed: rx2[I] = (rx[2I], rx[2I+1])
        u64 rx2[12];
#pragma unroll
        for (int I = 0; I < 12; I++) {
            u64 dx = fma2(scp[I][0], NEG1, gxx);
            u64 dy = fma2(scp[I][1], NEG1, gyy);
            u64 dz = fma2(scp[I][2], NEG1, gzz);
            u64 s  = mul2(dx, dx);
            s = fma2(dy, dy, s);
            s = fma2(dz, dz, s);
            float s0, s1; upk(s, s0, s1);
            rx2[I] = pk(s0 * rsqrt_a(s0), s1 * rsqrt_a(s1));
        }

        // cell2[I] = (cell[2I], cell[2I+1]); 0.5 prefactors dropped (cancel).
        u64 cell2[12];
#pragma unroll
        for (int I = 0; I < 12; I++) cell2[I] = ONE;

#pragma unroll
        for (int I = 0; I < 12; I++) {
            // diagonal pair (2I, 2I+1), scalar
            {
                float rlo, rhi; upk(rx2[I], rlo, rhi);
                float mu = (rlo - rhi) * ((const float*)&sAB[I][I].y)[0];
                float m  = mu * mu;
                mu = mu * fmaf(m, -0.5f, 1.5f);
                m  = mu * mu;
                mu = mu * fmaf(m, -0.5f, 1.5f);
                cell2[I] = mul2(cell2[I], pk(1.0f - mu, 1.0f + mu));
            }
#pragma unroll
            for (int J = I + 1; J < 12; J++) {
                const ulonglong2 ab = sAB[I][J];   // one LDS.128
                // aligned lanes: mu(2I,2J), mu(2I+1,2J+1)
                u64 muA = mul2(fma2(rx2[J], NEG1, rx2[I]), ab.x);
                // cross lanes:   mu(2I,2J+1), mu(2I+1,2J)
                u64 muB = mul2(fma2(swap2(rx2[J]), NEG1, rx2[I]), ab.y);

                u64 m2 = mul2(muA, muA);
                muA = mul2(muA, fma2(m2, CN05, C15));
                m2  = mul2(muA, muA);
                muA = mul2(muA, fma2(m2, CN05, C15));

                m2  = mul2(muB, muB);
                muB = mul2(muB, fma2(m2, CN05, C15));
                m2  = mul2(muB, muB);
                muB = mul2(muB, fma2(m2, CN05, C15));

                cell2[I] = mul2(cell2[I], fma2(muA, NEG1, ONE));
                cell2[I] = mul2(cell2[I], fma2(muB, NEG1, ONE));
                cell2[J] = mul2(cell2[J], add2(muA, ONE));
                cell2[J] = mul2(cell2[J], add2(swap2(muB), ONE));
            }
        }

        u64 s2 = cell2[0];
#pragma unroll
        for (int I = 1; I < 12; I++) s2 = add2(s2, cell2[I]);
        float slo, shi; upk(s2, slo, shi);
        const float ssum = slo + shi;

        const int Iam = am >> 1;
        u64 cam2 = cell2[0];
#pragma unroll
        for (int I = 1; I < 12; I++) if (I == Iam) cam2 = cell2[I];
        float clo, chi; upk(cam2, clo, chi);
        const float cam = (am & 1) ? chi : clo;

        out[W_OFF + nmol * MXP + p] = __fdividef(cam, ssum) * wt;
    } else {
        // ================= grid + dv streaming role =================
        const int dvb = blockIdx.x - BECKE_BLOCKS;
        const int gp0 = dvb * ROWS_PER_DVB;
        __syncthreads();                           // tables ready

        // Phase A: grid coords for 260 rows -> grid section + shared staging
        for (int lp = tid; lp < ROWS_PER_DVB; lp += 128) {
            const int gp = gp0 + lp;
            const int n  = gp / MXP;
            const int p  = gp - n * MXP;
            const int am = p / MS;
            const int k  = p - am * MS;
            const int a  = k / DESIGN;
            const int d  = k - a * DESIGN;

            const float r = r_tab[a];
            const float* ca = coords + (n * MA + am) * 3;
            const float gx = __ldg(ca + 0) + r * sph[d][0];
            const float gy = __ldg(ca + 1) + r * sph[d][1];
            const float gz = __ldg(ca + 2) + r * sph[d][2];

            out[3 * gp + 0] = gx;
            out[3 * gp + 1] = gy;
            out[3 * gp + 2] = gz;

            g6[lp][0] = gx; g6[lp][1] = gy; g6[lp][2] = gz;
            g6[lp][3] = gx; g6[lp][4] = gy; g6[lp][5] = gz;
            ns[lp] = (short)n;
        }
        __syncthreads();

        // Phase B: dv stores, linear float4 stream (perfect coalescing)
        const float4* c4base = (const float4*)coords;   // 18 float4 per mol
        float4* dst4 = (float4*)(out + DV_OFF) + gp0 * 18;
        const int total4 = ROWS_PER_DVB * 18;           // 4680

        for (int idx = tid; idx < total4; idx += 128) {
            const int lp = idx / 18;
            const int rr = idx - lp * 18;
            const int rm = rr % 3;

            const float pa = g6[lp][rm];
            const float pb = g6[lp][rm + 1];
            const float pc = g6[lp][rm + 2];
            const float4 c4 = __ldg(c4base + ns[lp] * 18 + rr);

            float4 o;
            o.x = pa - c4.x;
            o.y = pb - c4.y;
            o.z = pc - c4.z;
            o.w = pa - c4.w;
            dst4[idx] = o;
        }
    }
}

extern "C" void kernel_launch(void* const* d_in, const int* in_sizes, int n_in,
                              void* d_out, int out_size)
{
    // d_in[0]: labels (int32, unused -- padding is full for every molecule)
    const float* coords = (const float*)d_in[1];
    const float* sphere = (const float*)d_in[2];
    const float* sw     = (const float*)d_in[3];
    float* out = (float*)d_out;

    grid_kernel<<<BECKE_BLOCKS + DV_BLOCKS, 128>>>(coords, sphere, sw, out);
}